// round 7
// baseline (speedup 1.0000x reference)
#include <cuda_runtime.h>
#include <cuda_fp16.h>
#include <math.h>

#define BB    4
#define NN    1024
#define HID   64
#define HEADS 16
#define NBLK  148           // persistent: one block per SM

// Log2-spaced table indexed by float-bit pattern of squared distance.
// Segment idx <-> bits(sq): idx = (bits >> 17) - IDX_OFFSET, 64 nodes per octave of sq.
// Covers sq in [2^-20, 2^8]  (d in [~0.001, 16]); node 0 stores exact f(0).
#define TAB_ROWS   1792     // 28 octaves * 64
#define TAB_NODES  1793
#define IDX_OFFSET 6848     // (127 - 20) << 6

// Raw fp32 nodes: g_raw[n*4 + c] = float4 of heads 4c..4c+3 at distance d_n.
__device__ float4 g_raw[TAB_NODES * 4];

// Kernel 1: warp-per-node eval. Lanes split HID (2 h each), shfl-butterfly reduce.
__global__ __launch_bounds__(256)
void build_raw_kernel(const float* __restrict__ w1,
                      const float* __restrict__ b1,
                      const float* __restrict__ w2,
                      const float* __restrict__ b2) {
    int node = (blockIdx.x * blockDim.x + threadIdx.x) >> 5;
    int lane = threadIdx.x & 31;
    if (node >= TAB_NODES) return;

    float d;
    if (node == 0) {
        d = 0.0f;   // node 0 = exact f(0): diagonal pairs (sq==0, fr==0) become exact
    } else {
        int en = node >> 6;
        int mn = node & 63;
        float sq = exp2f((float)(en - 20)) * (1.0f + (float)mn * (1.0f / 64.0f));
        d = sqrtf(sq);
    }

    float acc[HEADS];
#pragma unroll
    for (int k = 0; k < HEADS; k++) acc[k] = 0.0f;

#pragma unroll
    for (int hh = 0; hh < HID / 32; hh++) {
        int h = lane + hh * 32;
        float a = fmaf(d, w1[h], b1[h]);
        float s = a / (1.0f + __expf(-a));   // silu
#pragma unroll
        for (int k = 0; k < HEADS; k++)
            acc[k] = fmaf(s, w2[h * HEADS + k], acc[k]);
    }

#pragma unroll
    for (int off = 16; off >= 1; off >>= 1) {
#pragma unroll
        for (int k = 0; k < HEADS; k++)
            acc[k] += __shfl_xor_sync(0xffffffffu, acc[k], off);
    }

    if (lane == 0) {
#pragma unroll
        for (int c = 0; c < 4; c++)
            g_raw[node * 4 + c] = make_float4(acc[c * 4 + 0] + b2[c * 4 + 0],
                                              acc[c * 4 + 1] + b2[c * 4 + 1],
                                              acc[c * 4 + 2] + b2[c * 4 + 2],
                                              acc[c * 4 + 3] + b2[c * 4 + 3]);
    }
}

// Kernel 2: persistent blocks (1/SM, 256 threads). Stage+pack table into smem
// (chunk-major fp16 endpoint pairs), then loop rows. NO sqrt anywhere:
// segment index and lerp fraction come straight from the bit pattern of d^2.
__global__ __launch_bounds__(256)
void bias_kernel(const float* __restrict__ coords, float* __restrict__ out) {
    extern __shared__ uint4 stab[];   // 4 * TAB_ROWS uint4 = 112 KB

    // One-time stage + fp16 pair-pack (raw table is L2-resident, ~115 KB).
#pragma unroll
    for (int c = 0; c < 4; c++) {
        for (int r = threadIdx.x; r < TAB_ROWS; r += 256) {
            float4 a = g_raw[r * 4 + c];
            float4 b = g_raw[(r + 1) * 4 + c];
            __half2 h0 = __floats2half2_rn(a.x, b.x);
            __half2 h1 = __floats2half2_rn(a.y, b.y);
            __half2 h2 = __floats2half2_rn(a.z, b.z);
            __half2 h3 = __floats2half2_rn(a.w, b.w);
            uint4 v;
            v.x = *(unsigned*)&h0; v.y = *(unsigned*)&h1;
            v.z = *(unsigned*)&h2; v.w = *(unsigned*)&h3;
            stab[c * TAB_ROWS + r] = v;
        }
    }
    __syncthreads();

    const int t = threadIdx.x;

    for (int row = blockIdx.x; row < BB * NN; row += NBLK) {
        int b = row >> 10;          // / NN
        int i = row & (NN - 1);

        const float* cb = coords + (size_t)b * NN * 3;
        float cix = cb[i * 3 + 0];
        float ciy = cb[i * 3 + 1];
        float ciz = cb[i * 3 + 2];

        // 4 consecutive j coords = 12 floats = 3 aligned float4 loads (cache-resident)
        const float4* cb4 = (const float4*)cb;
        float4 p0 = cb4[t * 3 + 0];
        float4 p1 = cb4[t * 3 + 1];
        float4 p2 = cb4[t * 3 + 2];

        float jx[4] = {p0.x, p0.w, p1.z, p2.y};
        float jy[4] = {p0.y, p1.x, p1.w, p2.z};
        float jz[4] = {p0.z, p1.y, p2.x, p2.w};

        float vv[HEADS][4];

#pragma unroll
        for (int jj = 0; jj < 4; jj++) {
            float dx = jx[jj] - cix;
            float dy = jy[jj] - ciy;
            float dz = jz[jj] - ciz;
            float sq = fmaf(dx, dx, fmaf(dy, dy, dz * dz));

            // Bit-hack log-spaced index: no sqrt, no MUFU.
            unsigned u = __float_as_uint(sq);
            int idx = (int)(u >> 17) - IDX_OFFSET;
            idx = min(max(idx, 0), TAB_ROWS - 1);
            float fr = (float)(u & 0x1FFFFu) * (1.0f / 131072.0f);

#pragma unroll
            for (int c = 0; c < 4; c++) {
                uint4 raw = stab[c * TAB_ROWS + idx];
#pragma unroll
                for (int q = 0; q < 4; q++) {
                    unsigned w = (q == 0) ? raw.x : (q == 1) ? raw.y
                               : (q == 2) ? raw.z : raw.w;
                    float2 pr = __half22float2(*(const __half2*)&w); // (f_lo, f_hi)
                    vv[c * 4 + q][jj] = fmaf(fr, pr.y - pr.x, pr.x);
                }
            }
        }

        // out[b][k][i][j], j = 4t..4t+3 : one STG.128 per head, fully coalesced
#pragma unroll
        for (int k = 0; k < HEADS; k++) {
            float4 o = make_float4(vv[k][0], vv[k][1], vv[k][2], vv[k][3]);
            size_t off = (((size_t)(b * HEADS + k) * NN + i) * NN) + 4 * t;
            *(float4*)(out + off) = o;
        }
    }
}

extern "C" void kernel_launch(void* const* d_in, const int* in_sizes, int n_in,
                              void* d_out, int out_size) {
    const float* coords = (const float*)d_in[0];
    const float* w1     = (const float*)d_in[1];
    const float* b1     = (const float*)d_in[2];
    const float* w2     = (const float*)d_in[3];
    const float* b2     = (const float*)d_in[4];
    float* out = (float*)d_out;

    static int smem_set = 0;
    if (!smem_set) {
        cudaFuncSetAttribute(bias_kernel,
                             cudaFuncAttributeMaxDynamicSharedMemorySize,
                             4 * TAB_ROWS * sizeof(uint4));
        smem_set = 1;
    }

    build_raw_kernel<<<(TAB_NODES * 32 + 255) / 256, 256>>>(w1, b1, w2, b2);
    bias_kernel<<<NBLK, 256, 4 * TAB_ROWS * sizeof(uint4)>>>(coords, out);
}